// round 1
// baseline (speedup 1.0000x reference)
#include <cuda_runtime.h>
#include <cstdint>

#define CHAR_EMB 30
#define NFILT    30
#define KSIZE    3
#define MAXW     40
#define NCHARS   102
#define POS_PER_BLK 8
#define CTHREADS (POS_PER_BLK * CHAR_EMB)   // 240

// ---------- packed f32x2 helpers (sm_103a) ----------
__device__ __forceinline__ unsigned long long pk2(float lo, float hi) {
    unsigned long long r;
    asm("mov.b64 %0, {%1, %2};" : "=l"(r) : "f"(lo), "f"(hi));
    return r;
}
__device__ __forceinline__ void upk2(float& lo, float& hi, unsigned long long v) {
    asm("mov.b64 {%0, %1}, %2;" : "=f"(lo), "=f"(hi) : "l"(v));
}
__device__ __forceinline__ unsigned long long fma2(unsigned long long a, unsigned long long b,
                                                   unsigned long long c) {
    unsigned long long d;
    asm("fma.rn.f32x2 %0, %1, %2, %3;" : "=l"(d) : "l"(a), "l"(b), "l"(c));
    return d;
}
__device__ __forceinline__ unsigned long long mul2(unsigned long long a, unsigned long long b) {
    unsigned long long d;
    asm("mul.rn.f32x2 %0, %1, %2;" : "=l"(d) : "l"(a), "l"(b));
    return d;
}

// ---------- conv + max-pool kernel ----------
// One thread handles one (position, group e). It computes all 30 filters of
// that group and writes out[pos*1000 + e*30 + f].
__global__ __launch_bounds__(CTHREADS)
void conv_pool_kernel(const int* __restrict__ char_ids,
                      const float* __restrict__ char_emb,
                      const float* __restrict__ conv_w,
                      const float* __restrict__ conv_b,
                      float* __restrict__ out,
                      int n_pos)
{
    __shared__ float emb_s[NCHARS * 32];          // [char][e] padded to 32
    __shared__ float w_s[900 * 4];                // [o] -> (w0,w1,w2,bias)
    __shared__ int   ids_s[POS_PER_BLK * MAXW];

    const int tid = threadIdx.x;
    const int pos_base = blockIdx.x * POS_PER_BLK;

    for (int i = tid; i < NCHARS * CHAR_EMB; i += CTHREADS)
        emb_s[(i / CHAR_EMB) * 32 + (i % CHAR_EMB)] = char_emb[i];
    for (int i = tid; i < 900 * KSIZE; i += CTHREADS)
        w_s[(i / KSIZE) * 4 + (i % KSIZE)] = conv_w[i];
    for (int i = tid; i < 900; i += CTHREADS)
        w_s[i * 4 + 3] = conv_b[i];
    for (int i = tid; i < POS_PER_BLK * MAXW; i += CTHREADS) {
        int gidx = pos_base * MAXW + i;
        ids_s[i] = (gidx < n_pos * MAXW) ? char_ids[gidx] : 0;
    }
    __syncthreads();

    const int e  = tid % CHAR_EMB;
    const int pl = tid / CHAR_EMB;
    const int pos = pos_base + pl;
    if (pos >= n_pos) return;

    // Gather this thread's row x[e][0..39] into registers.
    float xv[MAXW];
#pragma unroll
    for (int w = 0; w < MAXW; w++)
        xv[w] = emb_s[ids_s[pl * MAXW + w] * 32 + e];

    // Even-phase pairs (x[2i],x[2i+1]) and odd-phase pairs (x[2i+1],x[2i+2]).
    unsigned long long xe[20], xo[19];
#pragma unroll
    for (int i = 0; i < 20; i++) xe[i] = pk2(xv[2 * i], xv[2 * i + 1]);
#pragma unroll
    for (int i = 0; i < 19; i++) xo[i] = pk2(xv[2 * i + 1], xv[2 * i + 2]);

    float* outp = out + (size_t)pos * 1000 + e * NFILT;
    const float4* wrow = reinterpret_cast<const float4*>(w_s) + e * NFILT;

#pragma unroll 1
    for (int f = 0; f < NFILT; f++) {
        const float4 w = wrow[f];
        const unsigned long long w0 = pk2(w.x, w.x);
        const unsigned long long w1 = pk2(w.y, w.y);
        const unsigned long long w2 = pk2(w.z, w.z);
        float m0 = -3.402823466e+38f, m1 = -3.402823466e+38f;
#pragma unroll
        for (int tp = 0; tp < 19; tp++) {
            // y[t]   = w0*x[t]   + w1*x[t+1] + w2*x[t+2],  t = 2*tp, 2*tp+1
            unsigned long long acc = mul2(w2, xe[tp + 1]);
            acc = fma2(w1, xo[tp], acc);
            acc = fma2(w0, xe[tp], acc);
            float lo, hi;
            upk2(lo, hi, acc);
            m0 = fmaxf(m0, lo);
            m1 = fmaxf(m1, hi);
        }
        outp[f] = fmaxf(m0, m1) + w.w;
    }
}

// ---------- glove gather kernel ----------
// out[pos, 900:1000] = glove[word_ids[pos], :], vectorized float4 (25 per row).
__global__ void glove_kernel(const int* __restrict__ word_ids,
                             const float4* __restrict__ glove4,
                             float4* __restrict__ out4,
                             int n_pos)
{
    int idx = blockIdx.x * blockDim.x + threadIdx.x;
    if (idx >= n_pos * 25) return;
    int pos = idx / 25;
    int j   = idx % 25;
    int wid = word_ids[pos];
    out4[(size_t)pos * 250 + 225 + j] = glove4[(size_t)wid * 25 + j];
}

extern "C" void kernel_launch(void* const* d_in, const int* in_sizes, int n_in,
                              void* d_out, int out_size)
{
    const int*   char_ids = (const int*)d_in[0];
    const int*   word_ids = (const int*)d_in[1];
    const float* char_emb = (const float*)d_in[2];
    const float* conv_w   = (const float*)d_in[3];
    const float* conv_b   = (const float*)d_in[4];
    const float* glove    = (const float*)d_in[5];
    float*       out      = (float*)d_out;

    const int n_pos = in_sizes[1];   // B*S = 8192

    int conv_blocks = (n_pos + POS_PER_BLK - 1) / POS_PER_BLK;
    conv_pool_kernel<<<conv_blocks, CTHREADS>>>(char_ids, char_emb, conv_w, conv_b, out, n_pos);

    int gl_threads = n_pos * 25;
    glove_kernel<<<(gl_threads + 255) / 256, 256>>>(word_ids,
                                                    (const float4*)glove,
                                                    (float4*)out, n_pos);
}